// round 16
// baseline (speedup 1.0000x reference)
#include <cuda_runtime.h>
#include <cuda_fp16.h>
#include <math.h>
#include <stdint.h>

// ---------------- problem constants ----------------
#define BT      3136
#define NJ      43
#define NJ6     13
#define DLAT    512
#define OUTC    168

// ---------------- tiling ----------------
#define TM       64       // tokens per CTA
#define NCHUNK   128      // N per chunk (4 chunks)
#define KCH      64       // K per B stage (8 k-stages per chunk)
#define NTHREADS 128      // 4 warps, warp tile m64 n32

// ---------------- smem layout (bytes), 2 CTAs/SM ----------------
#define OFF_A    0
#define A_SUB(k) ((k)*16384)               // 4 x [64][128] fp16, 256B-row BSWZ
#define OFF_B    65536
#define B_ST(b)  (OFF_B + (b)*16384)       // 2 stages x [64][128] fp16
#define OFF_B1   98304                     // 512 fp32
#define OFF_W2T  100352                    // [6][516] fp32
#define W2STR    516
#define OFF_RED  OFF_B                     // aliased (B dead at end)
#define SMEM_BYTES 112736

#define BSWZ(x) ((x) ^ (((x) >> 4) & 0x70))   // 256B rows: bits[4:6] ^= row&7

// ---------------- device scratch: preconverted fp16 ----------------
__device__ __half g_w1h[(size_t)NJ * DLAT * DLAT];
__device__ __half g_xh[(size_t)BT * NJ * DLAT];

__device__ __forceinline__ uint32_t smem_u32(const void* p) {
    uint32_t a;
    asm("{ .reg .u64 t; cvta.to.shared.u64 t, %1; cvt.u32.u64 %0, t; }" : "=r"(a) : "l"(p));
    return a;
}

__device__ __forceinline__ float gelu_erf(float v) {
    return 0.5f * v * (1.0f + erff(v * 0.70710678118654752f));
}

__device__ __forceinline__ uint32_t pkh(float a, float b) {
    return (uint32_t)__half_as_ushort(__float2half_rn(a))
         | ((uint32_t)__half_as_ushort(__float2half_rn(b)) << 16);
}

// ---------------- cp.async ----------------
__device__ __forceinline__ void cpa16(uint32_t dst, const void* src, int ssz) {
    asm volatile("cp.async.cg.shared.global [%0], [%1], 16, %2;"
                 :: "r"(dst), "l"(src), "r"(ssz) : "memory");
}
#define CP_COMMIT() asm volatile("cp.async.commit_group;" ::: "memory")
#define CP_WAIT0()  asm volatile("cp.async.wait_group 0;" ::: "memory")

// ---------------- mma / ldmatrix ----------------
__device__ __forceinline__ void ldsm4(uint32_t* r, uint32_t addr) {
    asm volatile("ldmatrix.sync.aligned.m8n8.x4.shared.b16 {%0,%1,%2,%3}, [%4];"
                 : "=r"(r[0]), "=r"(r[1]), "=r"(r[2]), "=r"(r[3]) : "r"(addr));
}
__device__ __forceinline__ void ldsm4t(uint32_t* r, uint32_t addr) {
    asm volatile("ldmatrix.sync.aligned.m8n8.x4.trans.shared.b16 {%0,%1,%2,%3}, [%4];"
                 : "=r"(r[0]), "=r"(r[1]), "=r"(r[2]), "=r"(r[3]) : "r"(addr));
}
__device__ __forceinline__ void mma16816(float* c, const uint32_t* a, const uint32_t* b) {
    asm volatile("mma.sync.aligned.m16n8k16.row.col.f32.f16.f16.f32 "
                 "{%0,%1,%2,%3}, {%4,%5,%6,%7}, {%8,%9}, {%0,%1,%2,%3};"
                 : "+f"(c[0]), "+f"(c[1]), "+f"(c[2]), "+f"(c[3])
                 : "r"(a[0]), "r"(a[1]), "r"(a[2]), "r"(a[3]), "r"(b[0]), "r"(b[1]));
}

// ---------------- merged preconvert kernel (W1 then x) -> fp16 ----------------
#define W1F4 2818048u      // 43*512*512/4
#define XF4  17260544u     // 3136*43*512/4
__global__ __launch_bounds__(512, 2)
void convert_all_kernel(const float* __restrict__ W1, const float* __restrict__ x) {
    const uint32_t idx = blockIdx.x * 512u + threadIdx.x;   // exact grid: W1F4+XF4
    if (idx < W1F4) {
        const float4 v = ((const float4*)W1)[idx];
        uint2 o;
        o.x = pkh(v.x, v.y);
        o.y = pkh(v.z, v.w);
        ((uint2*)g_w1h)[idx] = o;
    } else {
        const uint32_t i2 = idx - W1F4;
        const float4 v = ((const float4*)x)[i2];
        uint2 o;
        o.x = pkh(v.x, v.y);
        o.y = pkh(v.z, v.w);
        ((uint2*)g_xh)[i2] = o;
    }
}

// ---------------- A prefetch (runs once) ----------------
__device__ __forceinline__ void prefetch_a_all(uint32_t smb, int j, int tok0, int tid) {
    #pragma unroll
    for (int r = 0; r < 32; ++r) {
        const int idx = tid + r * NTHREADS;     // 0..4095
        const int m = idx >> 6;                 // token row (0..63)
        const int c = idx & 63;                 // 16B unit of K
        const int sub = c >> 4, w = c & 15;
        const int token = tok0 + m;
        const size_t g = ((size_t)token * NJ + j) * DLAT + c * 8;
        const int ssz = (token < BT) ? 16 : 0;
        const uint32_t o = A_SUB(sub) + BSWZ((uint32_t)(m * 256 + w * 16));
        cpa16(smb + o, g_xh + g, ssz);
    }
}

// ---------------- main kernel ----------------
__global__ __launch_bounds__(NTHREADS, 2)
void motion_decoder_mma(const float* __restrict__ b1,
                        const float* __restrict__ W2a,
                        const float* __restrict__ b2a,
                        const float* __restrict__ W2b,
                        const float* __restrict__ b2b,
                        float* __restrict__ out)
{
    extern __shared__ char sm[];
    const uint32_t smb = smem_u32(sm);
    const int tid = threadIdx.x;
    const int wn = tid >> 5, lane = tid & 31;   // 4 warps: n offset wn*32
    const int j = blockIdx.y;
    const int tok0 = blockIdx.x * TM;

    const int odim = (j < NJ6) ? 6 : 3;
    const float* W2 = (j < NJ6) ? (W2a + (size_t)j * DLAT * 6)
                                : (W2b + (size_t)(j - NJ6) * DLAT * 3);
    const float* b2 = (j < NJ6) ? (b2a + j * 6) : (b2b + (j - NJ6) * 3);
    const int colbase = (j < NJ6) ? j * 6 : (NJ6 * 6 + (j - NJ6) * 3);

    // ---- B prefetch incremental state ----
    // idx_r = tid + r*128 -> k = k0 + 8r (k0 = tid>>4, 0..7), n16 fixed.
    // smem: BSWZ(k*256 + n16*16) = o0 + 2048*r (mask invariant: 8r = 0 mod 8)
    // gmem: p + r*8*DLAT
    const int k0 = tid >> 4, n16 = tid & 15;
    const uint32_t bo0 = BSWZ((uint32_t)(k0 * 256 + n16 * 16));
    const __half* bp = g_w1h + (size_t)j * DLAT * DLAT + (size_t)k0 * DLAT + n16 * 8;

    // prologue: full A + B stage 0 in flight
    prefetch_a_all(smb, j, tok0, tid);
    {
        const uint32_t d = smb + B_ST(0) + bo0;
        #pragma unroll
        for (int r = 0; r < 8; ++r)
            cpa16(d + r * 2048, bp + (size_t)r * 8 * DLAT, 16);
        bp += 64 * DLAT;   // advance to stage 1
    }
    CP_COMMIT();

    // preload b1 and W2 (transposed to [o][n], zero-padded rows for odim==3)
    float* b1s = (float*)(sm + OFF_B1);
    for (int i = tid; i < DLAT; i += NTHREADS) b1s[i] = b1[j * DLAT + i];
    float* w2t = (float*)(sm + OFF_W2T);
    for (int i = tid; i < 6 * DLAT; i += NTHREADS) {
        const int o = i / DLAT, n = i - o * DLAT;
        w2t[o * W2STR + n] = (o < odim) ? W2[n * odim + o] : 0.f;
    }

    const int l15 = lane & 15;
    const int lhi = (lane >> 4) & 1;

    // precomputed swizzled fragment offsets (hoisted)
    uint32_t aoffp[4], boffp[2];
    #pragma unroll
    for (int mt = 0; mt < 4; ++mt) {
        const int row = mt * 16 + l15;
        aoffp[mt] = BSWZ((uint32_t)(row * 256 + lhi * 16));
    }
    #pragma unroll
    for (int nt2 = 0; nt2 < 2; ++nt2)
        boffp[nt2] = BSWZ((uint32_t)(l15 * 256 + wn * 64 + nt2 * 32 + lhi * 16));

    // GEMM2 accumulators: [mt][rowhalf][o]
    float oacc[4][2][6];
    #pragma unroll
    for (int a = 0; a < 4; ++a)
        #pragma unroll
        for (int b = 0; b < 2; ++b)
            #pragma unroll
            for (int o = 0; o < 6; ++o) oacc[a][b][o] = 0.f;

    #pragma unroll 1
    for (int nc = 0; nc < 4; ++nc) {
        float c[4][4][4];
        #pragma unroll
        for (int mt = 0; mt < 4; ++mt)
            #pragma unroll
            for (int nt = 0; nt < 4; ++nt)
                #pragma unroll
                for (int q = 0; q < 4; ++q) c[mt][nt][q] = 0.f;

        #pragma unroll 1
        for (int kc = 0; kc < 8; ++kc) {
            const int s = nc * 8 + kc;
            CP_WAIT0();                    // stage s B (and A on s=0) resident
            __syncthreads();               // visible; prior readers of buf done

            if (s < 31) {                  // prefetch B(s+1) during MMA(s)
                const int t = s + 1;
                const uint32_t d = smb + B_ST(t & 1) + bo0;
                #pragma unroll
                for (int r = 0; r < 8; ++r)
                    cpa16(d + r * 2048, bp + (size_t)r * 8 * DLAT, 16);
                CP_COMMIT();
                bp += 64 * DLAT;
                if ((t & 7) == 7) bp += 128 - 512 * DLAT;   // nc wrap
            }

            const uint32_t bb = smb + B_ST(s & 1);

            // register-pipelined fragments: load kt+1 while mma kt
            uint32_t ah[2][4][4], bh[2][2][4];
            {
                const int kg0 = kc * 4;
                const uint32_t ab = smb + A_SUB(kg0 >> 3);
                const uint32_t ainner = (uint32_t)((kg0 & 7) * 32);
                #pragma unroll
                for (int mt = 0; mt < 4; ++mt)
                    ldsm4(ah[0][mt], ab + (aoffp[mt] ^ ainner));
                #pragma unroll
                for (int nt2 = 0; nt2 < 2; ++nt2)
                    ldsm4t(bh[0][nt2], bb + boffp[nt2]);
            }
            #pragma unroll
            for (int kt = 0; kt < 4; ++kt) {
                const int cur = kt & 1, nxt = cur ^ 1;
                if (kt < 3) {
                    const int kg = kc * 4 + kt + 1;
                    const uint32_t ab = smb + A_SUB(kg >> 3);
                    const uint32_t ainner = (uint32_t)((kg & 7) * 32);
                    #pragma unroll
                    for (int mt = 0; mt < 4; ++mt)
                        ldsm4(ah[nxt][mt], ab + (aoffp[mt] ^ ainner));
                    #pragma unroll
                    for (int nt2 = 0; nt2 < 2; ++nt2)
                        ldsm4t(bh[nxt][nt2], bb + boffp[nt2] + ((uint32_t)(kt + 1) << 12));
                }
                #pragma unroll
                for (int mt = 0; mt < 4; ++mt)
                    #pragma unroll
                    for (int nt = 0; nt < 4; ++nt)
                        mma16816(c[mt][nt], ah[cur][mt], &bh[cur][nt >> 1][(nt & 1) * 2]);
            }
        }

        // ---- fused epilogue: bias + GELU + GEMM2 partial, registers only ----
        #pragma unroll
        for (int nt = 0; nt < 4; ++nt) {
            const int ncol = wn * 32 + nt * 8 + (lane & 3) * 2;
            const int ng = nc * NCHUNK + ncol;
            const float2 bv = *(const float2*)(b1s + ng);
            #pragma unroll
            for (int mt = 0; mt < 4; ++mt) {
                const float h0 = gelu_erf(c[mt][nt][0] + bv.x);
                const float h1 = gelu_erf(c[mt][nt][1] + bv.y);
                const float h2 = gelu_erf(c[mt][nt][2] + bv.x);
                const float h3 = gelu_erf(c[mt][nt][3] + bv.y);
                if (odim == 6) {
                    #pragma unroll
                    for (int o = 0; o < 6; ++o) {
                        const float2 w = *(const float2*)(w2t + o * W2STR + ng);
                        oacc[mt][0][o] += h0 * w.x + h1 * w.y;
                        oacc[mt][1][o] += h2 * w.x + h3 * w.y;
                    }
                } else {
                    #pragma unroll
                    for (int o = 0; o < 3; ++o) {
                        const float2 w = *(const float2*)(w2t + o * W2STR + ng);
                        oacc[mt][0][o] += h0 * w.x + h1 * w.y;
                        oacc[mt][1][o] += h2 * w.x + h3 * w.y;
                    }
                }
            }
        }
    }

    // ---- reduction: quad butterfly, then cross-warp via smem (aliased on B) ----
    #pragma unroll
    for (int mt = 0; mt < 4; ++mt)
        #pragma unroll
        for (int i = 0; i < 2; ++i)
            #pragma unroll
            for (int o = 0; o < 6; ++o) {
                float v = oacc[mt][i][o];
                v += __shfl_xor_sync(0xffffffffu, v, 1);
                v += __shfl_xor_sync(0xffffffffu, v, 2);
                oacc[mt][i][o] = v;
            }

    float* red = (float*)(sm + OFF_RED);
    __syncthreads();                       // all MMA done; no cp.async pending
    if ((lane & 3) == 0) {
        const int g = lane >> 2;
        #pragma unroll
        for (int mt = 0; mt < 4; ++mt)
            #pragma unroll
            for (int i = 0; i < 2; ++i) {
                const int row = mt * 16 + i * 8 + g;
                #pragma unroll
                for (int o = 0; o < 6; ++o)
                    red[(wn * TM + row) * 8 + o] = oacc[mt][i][o];
            }
    }
    __syncthreads();

    #pragma unroll
    for (int p = 0; p < 3; ++p) {
        const int idx = tid + p * NTHREADS;
        if (idx < TM * odim) {
            const int m = idx / odim;
            const int o = idx - m * odim;
            const int token = tok0 + m;
            if (token < BT) {
                const float sdm = red[m * 8 + o] + red[(TM + m) * 8 + o]
                                + red[(2 * TM + m) * 8 + o] + red[(3 * TM + m) * 8 + o];
                out[(size_t)token * OUTC + colbase + o] = sdm + b2[o];
            }
        }
    }
}

extern "C" void kernel_launch(void* const* d_in, const int* in_sizes, int n_in,
                              void* d_out, int out_size)
{
    const float* x   = (const float*)d_in[0];
    const float* W1  = (const float*)d_in[1];
    const float* b1  = (const float*)d_in[2];
    const float* W2a = (const float*)d_in[3];
    const float* b2a = (const float*)d_in[4];
    const float* W2b = (const float*)d_in[5];
    const float* b2b = (const float*)d_in[6];
    float* out = (float*)d_out;

    // 1) preconvert W1 + x to fp16, single launch (exact grid)
    convert_all_kernel<<<(W1F4 + XF4) / 512, 512>>>(W1, x);

    // 2) fused fp16 GEMM: m64n32 warp tiles, pipelined fragments, 2 CTAs/SM
    cudaFuncSetAttribute(motion_decoder_mma,
                         cudaFuncAttributeMaxDynamicSharedMemorySize, SMEM_BYTES);
    dim3 grid((BT + TM - 1) / TM, NJ);          // 49 x 43
    motion_decoder_mma<<<grid, NTHREADS, SMEM_BYTES>>>(b1, W2a, b2a, W2b, b2b, out);
}

// round 17
// speedup vs baseline: 1.1482x; 1.1482x over previous
#include <cuda_runtime.h>
#include <cuda_fp16.h>
#include <math.h>
#include <stdint.h>

// ---------------- problem constants ----------------
#define BT      3136
#define NJ      43
#define NJ6     13
#define DLAT    512
#define OUTC    168

// ---------------- tiling ----------------
#define TM       64       // tokens per CTA
#define NCHUNK   128      // N per chunk (4 chunks)
#define KCH      64       // K per B stage (8 k-stages per chunk)
#define NTHREADS 256      // 8 warps: 2 (m) x 4 (n), warp tile m32 n32

// ---------------- smem layout (bytes), 2 CTAs/SM ----------------
#define OFF_A    0
#define A_SUB(k) ((k)*16384)               // 4 x [64][128] fp16, 256B-row BSWZ
#define OFF_B    65536
#define B_ST(b)  (OFF_B + (b)*16384)       // 2 stages x [64][128] fp16
#define OFF_B1   98304                     // 512 fp32
#define OFF_W2T  100352                    // [6][516] fp32
#define W2STR    516
#define OFF_RED  OFF_B                     // aliased (B dead at end)
#define SMEM_BYTES 112736

#define BSWZ(x) ((x) ^ (((x) >> 4) & 0x70))   // 256B rows: bits[4:6] ^= row&7

// ---------------- device scratch: preconverted fp16 W1 only ----------------
__device__ __half g_w1h[(size_t)NJ * DLAT * DLAT];

__device__ __forceinline__ uint32_t smem_u32(const void* p) {
    uint32_t a;
    asm("{ .reg .u64 t; cvta.to.shared.u64 t, %1; cvt.u32.u64 %0, t; }" : "=r"(a) : "l"(p));
    return a;
}

__device__ __forceinline__ float gelu_erf(float v) {
    return 0.5f * v * (1.0f + erff(v * 0.70710678118654752f));
}

__device__ __forceinline__ uint32_t pkh(float a, float b) {
    return (uint32_t)__half_as_ushort(__float2half_rn(a))
         | ((uint32_t)__half_as_ushort(__float2half_rn(b)) << 16);
}

// ---------------- cp.async ----------------
__device__ __forceinline__ void cpa16(uint32_t dst, const void* src, int ssz) {
    asm volatile("cp.async.cg.shared.global [%0], [%1], 16, %2;"
                 :: "r"(dst), "l"(src), "r"(ssz) : "memory");
}
#define CP_COMMIT() asm volatile("cp.async.commit_group;" ::: "memory")
#define CP_WAIT0()  asm volatile("cp.async.wait_group 0;" ::: "memory")

// ---------------- mma / ldmatrix ----------------
__device__ __forceinline__ void ldsm4(uint32_t* r, uint32_t addr) {
    asm volatile("ldmatrix.sync.aligned.m8n8.x4.shared.b16 {%0,%1,%2,%3}, [%4];"
                 : "=r"(r[0]), "=r"(r[1]), "=r"(r[2]), "=r"(r[3]) : "r"(addr));
}
__device__ __forceinline__ void ldsm4t(uint32_t* r, uint32_t addr) {
    asm volatile("ldmatrix.sync.aligned.m8n8.x4.trans.shared.b16 {%0,%1,%2,%3}, [%4];"
                 : "=r"(r[0]), "=r"(r[1]), "=r"(r[2]), "=r"(r[3]) : "r"(addr));
}
__device__ __forceinline__ void mma16816(float* c, const uint32_t* a, const uint32_t* b) {
    asm volatile("mma.sync.aligned.m16n8k16.row.col.f32.f16.f16.f32 "
                 "{%0,%1,%2,%3}, {%4,%5,%6,%7}, {%8,%9}, {%0,%1,%2,%3};"
                 : "+f"(c[0]), "+f"(c[1]), "+f"(c[2]), "+f"(c[3])
                 : "r"(a[0]), "r"(a[1]), "r"(a[2]), "r"(a[3]), "r"(b[0]), "r"(b[1]));
}

// ---------------- W1 preconvert kernel (x handled in main kernel) ----------------
#define W1F4 2818048u      // 43*512*512/4
__global__ __launch_bounds__(512, 2)
void convert_w1_kernel(const float* __restrict__ W1) {
    const uint32_t idx = blockIdx.x * 512u + threadIdx.x;   // exact grid
    const float4 v = ((const float4*)W1)[idx];
    uint2 o;
    o.x = pkh(v.x, v.y);
    o.y = pkh(v.z, v.w);
    ((uint2*)g_w1h)[idx] = o;
}

// ---------------- A tile: fp32 gmem -> fp16 swizzled smem (once per CTA) ----------------
__device__ __forceinline__ void convert_a_all(char* sm, const float* __restrict__ x,
                                              int j, int tok0, int tid) {
    #pragma unroll
    for (int r = 0; r < 16; ++r) {
        const int idx = tid + r * NTHREADS;     // 0..4095
        const int m = idx >> 6;                 // token row (0..63)
        const int c = idx & 63;                 // 16B fp16 unit of K (8 elems)
        const int sub = c >> 4, w = c & 15;
        const int token = tok0 + m;
        uint4 val = make_uint4(0u, 0u, 0u, 0u);
        if (token < BT) {
            const float4* src = (const float4*)(x + ((size_t)token * NJ + j) * DLAT + c * 8);
            const float4 v0 = src[0], v1 = src[1];
            val.x = pkh(v0.x, v0.y); val.y = pkh(v0.z, v0.w);
            val.z = pkh(v1.x, v1.y); val.w = pkh(v1.z, v1.w);
        }
        *(uint4*)(sm + A_SUB(sub) + BSWZ((uint32_t)(m * 256 + w * 16))) = val;
    }
}

// ---------------- main kernel ----------------
__global__ __launch_bounds__(NTHREADS, 2)
void motion_decoder_mma(const float* __restrict__ x,
                        const float* __restrict__ b1,
                        const float* __restrict__ W2a,
                        const float* __restrict__ b2a,
                        const float* __restrict__ W2b,
                        const float* __restrict__ b2b,
                        float* __restrict__ out)
{
    extern __shared__ char sm[];
    const uint32_t smb = smem_u32(sm);
    const int tid = threadIdx.x;
    const int wid = tid >> 5, lane = tid & 31;
    const int wm = wid >> 2;               // 0..1 -> m offset wm*32
    const int wn = wid & 3;                // 0..3 -> n offset wn*32
    const int j = blockIdx.y;
    const int tok0 = blockIdx.x * TM;

    const int odim = (j < NJ6) ? 6 : 3;
    const float* W2 = (j < NJ6) ? (W2a + (size_t)j * DLAT * 6)
                                : (W2b + (size_t)(j - NJ6) * DLAT * 3);
    const float* b2 = (j < NJ6) ? (b2a + j * 6) : (b2b + (j - NJ6) * 3);
    const int colbase = (j < NJ6) ? j * 6 : (NJ6 * 6 + (j - NJ6) * 3);

    // ---- B prefetch incremental state (hoisted address math) ----
    const int k0 = tid >> 4, n16 = tid & 15;
    const uint32_t bo0 = BSWZ((uint32_t)(k0 * 256 + n16 * 16));
    const __half* bp = g_w1h + (size_t)j * DLAT * DLAT + (size_t)k0 * DLAT + n16 * 8;

    // prologue: B stage 0 in flight FIRST (overlaps the A convert below)
    {
        const uint32_t d = smb + B_ST(0) + bo0;
        cpa16(d,            bp,               16);
        cpa16(d + 4096,     bp + 16 * DLAT,   16);
        cpa16(d + 8192,     bp + 32 * DLAT,   16);
        cpa16(d + 12288,    bp + 48 * DLAT,   16);
        bp += 64 * DLAT;   // advance to stage 1
    }
    CP_COMMIT();

    // A tile: direct fp32 load + convert + swizzled store (once)
    convert_a_all(sm, x, j, tok0, tid);

    // preload b1 and W2 (transposed to [o][n], zero-padded rows for odim==3)
    float* b1s = (float*)(sm + OFF_B1);
    for (int i = tid; i < DLAT; i += NTHREADS) b1s[i] = b1[j * DLAT + i];
    float* w2t = (float*)(sm + OFF_W2T);
    for (int i = tid; i < 6 * DLAT; i += NTHREADS) {
        const int o = i / DLAT, n = i - o * DLAT;
        w2t[o * W2STR + n] = (o < odim) ? W2[n * odim + o] : 0.f;
    }

    const int l15 = lane & 15;
    const int lhi = (lane >> 4) & 1;

    // precomputed swizzled fragment offsets (hoisted)
    uint32_t aoffp[2], boffp[2];
    #pragma unroll
    for (int mt = 0; mt < 2; ++mt) {
        const int row = wm * 32 + mt * 16 + l15;
        aoffp[mt] = BSWZ((uint32_t)(row * 256 + lhi * 16));
    }
    #pragma unroll
    for (int nt2 = 0; nt2 < 2; ++nt2)
        boffp[nt2] = BSWZ((uint32_t)(l15 * 256 + wn * 64 + nt2 * 32 + lhi * 16));

    // GEMM2 accumulators: [mt][rowhalf][o]
    float oacc[2][2][6];
    #pragma unroll
    for (int a = 0; a < 2; ++a)
        #pragma unroll
        for (int b = 0; b < 2; ++b)
            #pragma unroll
            for (int o = 0; o < 6; ++o) oacc[a][b][o] = 0.f;

    #pragma unroll 1
    for (int nc = 0; nc < 4; ++nc) {
        float c[2][4][4];
        #pragma unroll
        for (int mt = 0; mt < 2; ++mt)
            #pragma unroll
            for (int nt = 0; nt < 4; ++nt)
                #pragma unroll
                for (int q = 0; q < 4; ++q) c[mt][nt][q] = 0.f;

        #pragma unroll 1
        for (int kc = 0; kc < 8; ++kc) {
            const int s = nc * 8 + kc;
            CP_WAIT0();                    // stage s B resident
            __syncthreads();               // A stores + B visible; prior readers done

            if (s < 31) {                  // prefetch B(s+1) during MMA(s)
                const int t = s + 1;
                const uint32_t d = smb + B_ST(t & 1) + bo0;
                cpa16(d,         bp,             16);
                cpa16(d + 4096,  bp + 16 * DLAT, 16);
                cpa16(d + 8192,  bp + 32 * DLAT, 16);
                cpa16(d + 12288, bp + 48 * DLAT, 16);
                CP_COMMIT();
                bp += 64 * DLAT;
                if ((t & 7) == 7) bp += 128 - 512 * DLAT;   // nc wrap
            }

            const uint32_t bb = smb + B_ST(s & 1);

            #pragma unroll
            for (int kt = 0; kt < 4; ++kt) {
                const int kg = kc * 4 + kt;          // global k16 index 0..31
                const uint32_t ab = smb + A_SUB(kg >> 3);
                const uint32_t ainner = (uint32_t)((kg & 7) * 32);
                uint32_t ah[2][4], bh[2][4];
                #pragma unroll
                for (int mt = 0; mt < 2; ++mt)
                    ldsm4(ah[mt], ab + (aoffp[mt] ^ ainner));
                #pragma unroll
                for (int nt2 = 0; nt2 < 2; ++nt2)
                    ldsm4t(bh[nt2], bb + boffp[nt2] + ((uint32_t)kt << 12));
                #pragma unroll
                for (int mt = 0; mt < 2; ++mt)
                    #pragma unroll
                    for (int nt = 0; nt < 4; ++nt)
                        mma16816(c[mt][nt], ah[mt], &bh[nt >> 1][(nt & 1) * 2]);
            }
        }

        // ---- fused epilogue: bias + GELU + GEMM2 partial, registers only ----
        #pragma unroll
        for (int nt = 0; nt < 4; ++nt) {
            const int ncol = wn * 32 + nt * 8 + (lane & 3) * 2;
            const int ng = nc * NCHUNK + ncol;
            const float2 bv = *(const float2*)(b1s + ng);
            #pragma unroll
            for (int mt = 0; mt < 2; ++mt) {
                const float h0 = gelu_erf(c[mt][nt][0] + bv.x);
                const float h1 = gelu_erf(c[mt][nt][1] + bv.y);
                const float h2 = gelu_erf(c[mt][nt][2] + bv.x);
                const float h3 = gelu_erf(c[mt][nt][3] + bv.y);
                if (odim == 6) {
                    #pragma unroll
                    for (int o = 0; o < 6; ++o) {
                        const float2 w = *(const float2*)(w2t + o * W2STR + ng);
                        oacc[mt][0][o] += h0 * w.x + h1 * w.y;
                        oacc[mt][1][o] += h2 * w.x + h3 * w.y;
                    }
                } else {
                    #pragma unroll
                    for (int o = 0; o < 3; ++o) {
                        const float2 w = *(const float2*)(w2t + o * W2STR + ng);
                        oacc[mt][0][o] += h0 * w.x + h1 * w.y;
                        oacc[mt][1][o] += h2 * w.x + h3 * w.y;
                    }
                }
            }
        }
    }

    // ---- reduction: quad butterfly, then cross-warp via smem (aliased on B) ----
    #pragma unroll
    for (int mt = 0; mt < 2; ++mt)
        #pragma unroll
        for (int i = 0; i < 2; ++i)
            #pragma unroll
            for (int o = 0; o < 6; ++o) {
                float v = oacc[mt][i][o];
                v += __shfl_xor_sync(0xffffffffu, v, 1);
                v += __shfl_xor_sync(0xffffffffu, v, 2);
                oacc[mt][i][o] = v;
            }

    float* red = (float*)(sm + OFF_RED);
    __syncthreads();                       // all MMA done; no cp.async pending
    if ((lane & 3) == 0) {
        const int g = lane >> 2;
        #pragma unroll
        for (int mt = 0; mt < 2; ++mt)
            #pragma unroll
            for (int i = 0; i < 2; ++i) {
                const int row = wm * 32 + mt * 16 + i * 8 + g;
                #pragma unroll
                for (int o = 0; o < 6; ++o)
                    red[(wn * TM + row) * 8 + o] = oacc[mt][i][o];
            }
    }
    __syncthreads();

    #pragma unroll
    for (int p = 0; p < 2; ++p) {
        const int idx = tid + p * NTHREADS;
        if (idx < TM * odim) {
            const int m = idx / odim;
            const int o = idx - m * odim;
            const int token = tok0 + m;
            if (token < BT) {
                const float sdm = red[m * 8 + o] + red[(TM + m) * 8 + o]
                                + red[(2 * TM + m) * 8 + o] + red[(3 * TM + m) * 8 + o];
                out[(size_t)token * OUTC + colbase + o] = sdm + b2[o];
            }
        }
    }
}

extern "C" void kernel_launch(void* const* d_in, const int* in_sizes, int n_in,
                              void* d_out, int out_size)
{
    const float* x   = (const float*)d_in[0];
    const float* W1  = (const float*)d_in[1];
    const float* b1  = (const float*)d_in[2];
    const float* W2a = (const float*)d_in[3];
    const float* b2a = (const float*)d_in[4];
    const float* W2b = (const float*)d_in[5];
    const float* b2b = (const float*)d_in[6];
    float* out = (float*)d_out;

    // 1) preconvert W1 only (x converted in-kernel, once per CTA)
    convert_w1_kernel<<<W1F4 / 512, 512>>>(W1);

    // 2) fused fp16 GEMM: A resident (in-kernel convert), 2 CTAs/SM
    cudaFuncSetAttribute(motion_decoder_mma,
                         cudaFuncAttributeMaxDynamicSharedMemorySize, SMEM_BYTES);
    dim3 grid((BT + TM - 1) / TM, NJ);          // 49 x 43
    motion_decoder_mma<<<grid, NTHREADS, SMEM_BYTES>>>(x, b1, W2a, b2a, W2b, b2b, out);
}